// round 6
// baseline (speedup 1.0000x reference)
#include <cuda_runtime.h>
#include <cuda_fp16.h>
#include <cstdint>

#define DIM   2048
#define HID   8192
#define BATCH 4096

// ---------------- GEMM tiling ----------------
#define BM 128
#define BN 256
#define BK 32                      // fp16 K elements per stage
#define SROW 80                    // 64B data + 16B pad per row
#define STAGES 4
#define A_STG (BM * SROW)          // 10240 B
#define B_STG (BN * SROW)          // 20480 B
#define STG   (A_STG + B_STG)      // 30720 B
#define GEMM_SMEM (STAGES * STG)   // 122880 B

// s is scaled by 1/SSCALE before the final GEMM to avoid fp16 overflow
#define SSCALE 64.0f

// ---------------- device scratch ----------------
__device__ __align__(256) __half g_wf [DIM*DIM];
__device__ __align__(256) __half g_wc [DIM*DIM];
__device__ __align__(256) __half g_wg [DIM*DIM];
__device__ __align__(256) __half g_wo [DIM*DIM];
__device__ __align__(256) __half g_wu [HID*DIM];
__device__ __align__(256) __half g_wg2[HID*DIM];
__device__ __align__(256) __half g_wout[DIM*HID];

__device__ __align__(256) __half g_xhi[BATCH*DIM], g_xlo[BATCH*DIM];
__device__ __align__(256) float g_F[BATCH*DIM], g_C[BATCH*DIM], g_G[BATCH*DIM];
__device__ __align__(256) __half g_thi[BATCH*DIM], g_tlo[BATCH*DIM];
__device__ __align__(256) float g_O[BATCH*DIM];
__device__ __align__(256) __half g_ohi[BATCH*DIM], g_olo[BATCH*DIM];
__device__ __align__(256) float g_GG[BATCH*HID], g_U[BATCH*HID];
__device__ __align__(256) __half g_shi[BATCH*HID], g_slo[BATCH*HID];

// ---------------- PTX helpers ----------------
__device__ __forceinline__ uint32_t smem_u32(const void* p) {
    uint32_t a;
    asm("{ .reg .u64 t; cvta.to.shared.u64 t, %1; cvt.u32.u64 %0, t; }" : "=r"(a) : "l"(p));
    return a;
}
__device__ __forceinline__ void cp_async16(uint32_t s, const void* g) {
    asm volatile("cp.async.cg.shared.global [%0], [%1], 16;\n" :: "r"(s), "l"(g) : "memory");
}
__device__ __forceinline__ void cp_commit() {
    asm volatile("cp.async.commit_group;\n" ::: "memory");
}
__device__ __forceinline__ void ldsm_x4(uint32_t* r, uint32_t a) {
    asm volatile("ldmatrix.sync.aligned.m8n8.x4.shared.b16 {%0,%1,%2,%3}, [%4];\n"
                 : "=r"(r[0]), "=r"(r[1]), "=r"(r[2]), "=r"(r[3]) : "r"(a));
}
__device__ __forceinline__ void mma_f16(float* c, const uint32_t* a, const uint32_t* b) {
    asm volatile(
        "mma.sync.aligned.m16n8k16.row.col.f32.f16.f16.f32 "
        "{%0,%1,%2,%3}, {%4,%5,%6,%7}, {%8,%9}, {%0,%1,%2,%3};\n"
        : "+f"(c[0]), "+f"(c[1]), "+f"(c[2]), "+f"(c[3])
        : "r"(a[0]), "r"(a[1]), "r"(a[2]), "r"(a[3]), "r"(b[0]), "r"(b[1]));
}

// ---------------- elementwise ----------------
__device__ __forceinline__ float sigmoidf_(float v) { return 1.0f / (1.0f + expf(-v)); }

struct TernArgs {
    const float* src[7];
    __half*      dst[7];
};

// One kernel ternarizes all 7 weight matrices.
__global__ void tern_all_kernel(TernArgs args) {
    const int ndd = DIM * DIM / 8;
    const int nhd = HID * DIM / 8;
    long i = (long)blockIdx.x * blockDim.x + threadIdx.x;
    long total = 4L * ndd + 3L * nhd;
    if (i >= total) return;
    int seg; long off;
    if (i < 4L * ndd) { seg = (int)(i / ndd); off = i - (long)seg * ndd; }
    else { long j = i - 4L * ndd; seg = 4 + (int)(j / nhd); off = j - (long)(seg - 4) * nhd; }
    const float4* s = (const float4*)args.src[seg];
    uint4* d = (uint4*)args.dst[seg];
    float4 a = s[2*off], b = s[2*off+1];
    float v[8] = {a.x, a.y, a.z, a.w, b.x, b.y, b.z, b.w};
    union { uint4 u; __half h[8]; } r;
    #pragma unroll
    for (int j = 0; j < 8; j++) {
        float t = (fabsf(v[j]) < 0.33f) ? 0.0f : (v[j] > 0.0f ? 1.0f : -1.0f);
        r.h[j] = __float2half_rn(t);
    }
    d[off] = r.u;
}

// fp32 -> (hi, lo) fp16 pair
__global__ void split_kernel(const float4* __restrict__ v,
                             uint4* __restrict__ hi, uint4* __restrict__ lo, int n8) {
    int i = blockIdx.x * blockDim.x + threadIdx.x;
    if (i >= n8) return;
    float4 a = v[2*i], b = v[2*i+1];
    float x[8] = {a.x, a.y, a.z, a.w, b.x, b.y, b.z, b.w};
    union { uint4 u; __half h[8]; } rh, rl;
    #pragma unroll
    for (int j = 0; j < 8; j++) {
        __half h = __float2half_rn(x[j]);
        rh.h[j] = h;
        rl.h[j] = __float2half_rn(x[j] - __half2float(h));
    }
    hi[i] = rh.u; lo[i] = rl.u;
}

__global__ void mlgru_ew_kernel(int n4) {
    int i = blockIdx.x * blockDim.x + threadIdx.x;
    if (i >= n4) return;
    float4 f4 = ((const float4*)g_F)[i];
    float4 c4 = ((const float4*)g_C)[i];
    float4 g4 = ((const float4*)g_G)[i];
    float fv[4] = {f4.x, f4.y, f4.z, f4.w};
    float cv[4] = {c4.x, c4.y, c4.z, c4.w};
    float gv[4] = {g4.x, g4.y, g4.z, g4.w};
    union { uint2 u; __half h[4]; } rh, rl;
    #pragma unroll
    for (int j = 0; j < 4; j++) {
        float f = sigmoidf_(fv[j]);
        float c = cv[j] * sigmoidf_(cv[j]);
        float g = sigmoidf_(gv[j]);
        float t = g * (1.0f - f) * c;
        __half h = __float2half_rn(t);
        rh.h[j] = h;
        rl.h[j] = __float2half_rn(t - __half2float(h));
    }
    ((uint2*)g_thi)[i] = rh.u;
    ((uint2*)g_tlo)[i] = rl.u;
}

// s = sigmoid(GG)*silu(U) / SSCALE, hi/lo fp16
__global__ void glu_ew_kernel(int n4) {
    int i = blockIdx.x * blockDim.x + threadIdx.x;
    if (i >= n4) return;
    float4 gg4 = ((const float4*)g_GG)[i];
    float4 u4  = ((const float4*)g_U)[i];
    float ggv[4] = {gg4.x, gg4.y, gg4.z, gg4.w};
    float uv[4]  = {u4.x, u4.y, u4.z, u4.w};
    union { uint2 u; __half h[4]; } rh, rl;
    #pragma unroll
    for (int j = 0; j < 4; j++) {
        float gg = sigmoidf_(ggv[j]);
        float u  = uv[j] * sigmoidf_(uv[j]);
        float s  = gg * u * (1.0f / SSCALE);
        __half h = __float2half_rn(s);
        rh.h[j] = h;
        rl.h[j] = __float2half_rn(s - __half2float(h));
    }
    ((uint2*)g_shi)[i] = rh.u;
    ((uint2*)g_slo)[i] = rl.u;
}

// ---------------- HMMA GEMM --------------------------------------------------
// out[M,N] = alpha * ((Ahi ++ Alo)[M,2K] @ (W ++ W)[N,2K]^T) + bias  (fp32 out)
// CTA 128x256, 512 threads, warp tile 32x64, 4-stage cp.async pipeline.
__global__ __launch_bounds__(512, 1) void gemm_hmma(
    const __half* __restrict__ Ahi,
    const __half* __restrict__ Alo,
    const __half* __restrict__ W,
    const float* __restrict__ bias,
    float* __restrict__ out,
    int M, int N, int K, float alpha)
{
    extern __shared__ __align__(16) unsigned char smem[];

    const int tid  = threadIdx.x;
    const int lane = tid & 31;
    const int warp = tid >> 5;      // 0..15
    const int wm   = warp & 3;      // M band: 32 rows
    const int wn   = warp >> 2;     // N band: 64 cols
    const long bM  = (long)blockIdx.y * BM;
    const long bN  = (long)blockIdx.x * BN;

    const int ktH = K / BK;
    const int KT  = 2 * ktH;        // hi pass then lo pass

    float acc[2][8][4];
    #pragma unroll
    for (int i = 0; i < 2; i++)
        #pragma unroll
        for (int j = 0; j < 8; j++)
            #pragma unroll
            for (int k = 0; k < 4; k++) acc[i][j][k] = 0.0f;

    auto issue_tile = [&](int it_) {
        const __half* Ab = (it_ < ktH) ? Ahi : Alo;
        long kk = (long)(it_ < ktH ? it_ : it_ - ktH) * BK;
        unsigned char* s = smem + (it_ & (STAGES - 1)) * STG;
        #pragma unroll
        for (int c = tid; c < (BM + BN) * 4; c += 512) {
            int isB = (c >= BM * 4);
            int cc  = isB ? c - BM * 4 : c;
            int row = cc >> 2, kc = cc & 3;
            const __half* g = isB
                ? (W  + (bN + row) * (long)K + kk + kc * 8)
                : (Ab + (bM + row) * (long)K + kk + kc * 8);
            cp_async16(smem_u32(s + (isB ? A_STG : 0) + row * SROW + kc * 16), g);
        }
        cp_commit();
    };

    issue_tile(0); issue_tile(1); issue_tile(2);

    const int g1 = (lane >> 3) & 1;
    const int g2 = lane >> 4;
    const int r8 = lane & 7;

    for (int it = 0; it < KT; it++) {
        if (it + 2 < KT)      asm volatile("cp.async.wait_group 2;\n" ::: "memory");
        else if (it + 1 < KT) asm volatile("cp.async.wait_group 1;\n" ::: "memory");
        else                  asm volatile("cp.async.wait_group 0;\n" ::: "memory");
        __syncthreads();
        if (it + 3 < KT) issue_tile(it + 3);

        unsigned char* sA = smem + (it & (STAGES - 1)) * STG;
        unsigned char* sB = sA + A_STG;

        #pragma unroll
        for (int ks = 0; ks < 2; ks++) {
            uint32_t aF[2][4], bF[8][2];
            #pragma unroll
            for (int mi = 0; mi < 2; mi++) {
                int r = wm * 32 + mi * 16 + g1 * 8 + r8;
                int c = ks * 2 + g2;
                ldsm_x4(aF[mi], smem_u32(sA + r * SROW + c * 16));
            }
            #pragma unroll
            for (int nb = 0; nb < 4; nb++) {
                int r = wn * 64 + nb * 16 + g2 * 8 + r8;
                int c = ks * 2 + g1;
                uint32_t t[4];
                ldsm_x4(t, smem_u32(sB + r * SROW + c * 16));
                bF[nb * 2 + 0][0] = t[0]; bF[nb * 2 + 0][1] = t[1];
                bF[nb * 2 + 1][0] = t[2]; bF[nb * 2 + 1][1] = t[3];
            }
            #pragma unroll
            for (int mi = 0; mi < 2; mi++)
                #pragma unroll
                for (int nj = 0; nj < 8; nj++)
                    mma_f16(acc[mi][nj], aF[mi], bF[nj]);
        }
    }

    // epilogue: alpha*acc + bias, fp32 store
    const int cg = lane >> 2, tg = lane & 3;
    #pragma unroll
    for (int mi = 0; mi < 2; mi++) {
        #pragma unroll
        for (int nj = 0; nj < 8; nj++) {
            long row = bM + wm * 32 + mi * 16 + cg;
            long col = bN + wn * 64 + nj * 8 + tg * 2;
            float b0 = bias[col], b1 = bias[col + 1];
            float2 v0 = make_float2(fmaf(alpha, acc[mi][nj][0], b0),
                                    fmaf(alpha, acc[mi][nj][1], b1));
            float2 v1 = make_float2(fmaf(alpha, acc[mi][nj][2], b0),
                                    fmaf(alpha, acc[mi][nj][3], b1));
            *reinterpret_cast<float2*>(out + row * (long)N + col)       = v0;
            *reinterpret_cast<float2*>(out + (row + 8) * (long)N + col) = v1;
        }
    }
}

// ---------------- host launcher ----------------
extern "C" void kernel_launch(void* const* d_in, const int* in_sizes, int n_in,
                              void* d_out, int out_size)
{
    (void)in_sizes; (void)n_in; (void)out_size;
    const float* x    = (const float*)d_in[0];
    const float* wf   = (const float*)d_in[1];
    const float* bf_  = (const float*)d_in[2];
    const float* wc   = (const float*)d_in[3];
    const float* bc   = (const float*)d_in[4];
    const float* wg   = (const float*)d_in[5];
    const float* bg   = (const float*)d_in[6];
    const float* wo   = (const float*)d_in[7];
    const float* bo   = (const float*)d_in[8];
    const float* wu   = (const float*)d_in[9];
    const float* bu   = (const float*)d_in[10];
    const float* wg2  = (const float*)d_in[11];
    const float* bg2  = (const float*)d_in[12];
    const float* wout = (const float*)d_in[13];
    const float* bout = (const float*)d_in[14];
    float* out = (float*)d_out;

    cudaFuncSetAttribute(gemm_hmma, cudaFuncAttributeMaxDynamicSharedMemorySize, GEMM_SMEM);

    void *p_wf, *p_wc, *p_wg, *p_wo, *p_wu, *p_wg2, *p_wout;
    void *p_xhi, *p_xlo, *p_F, *p_C, *p_G, *p_thi, *p_tlo;
    void *p_O, *p_ohi, *p_olo, *p_GG, *p_U, *p_shi, *p_slo;
    cudaGetSymbolAddress(&p_wf, g_wf);     cudaGetSymbolAddress(&p_wc, g_wc);
    cudaGetSymbolAddress(&p_wg, g_wg);     cudaGetSymbolAddress(&p_wo, g_wo);
    cudaGetSymbolAddress(&p_wu, g_wu);     cudaGetSymbolAddress(&p_wg2, g_wg2);
    cudaGetSymbolAddress(&p_wout, g_wout);
    cudaGetSymbolAddress(&p_xhi, g_xhi);   cudaGetSymbolAddress(&p_xlo, g_xlo);
    cudaGetSymbolAddress(&p_F, g_F);       cudaGetSymbolAddress(&p_C, g_C);
    cudaGetSymbolAddress(&p_G, g_G);
    cudaGetSymbolAddress(&p_thi, g_thi);   cudaGetSymbolAddress(&p_tlo, g_tlo);
    cudaGetSymbolAddress(&p_O, g_O);
    cudaGetSymbolAddress(&p_ohi, g_ohi);   cudaGetSymbolAddress(&p_olo, g_olo);
    cudaGetSymbolAddress(&p_GG, g_GG);     cudaGetSymbolAddress(&p_U, g_U);
    cudaGetSymbolAddress(&p_shi, g_shi);   cudaGetSymbolAddress(&p_slo, g_slo);

    const int T = 256;
    const int nBD = BATCH * DIM, nBH = BATCH * HID;

    // 1) all ternarizations in ONE launch
    TernArgs ta;
    ta.src[0] = wf;   ta.dst[0] = (__half*)p_wf;
    ta.src[1] = wc;   ta.dst[1] = (__half*)p_wc;
    ta.src[2] = wg;   ta.dst[2] = (__half*)p_wg;
    ta.src[3] = wo;   ta.dst[3] = (__half*)p_wo;
    ta.src[4] = wu;   ta.dst[4] = (__half*)p_wu;
    ta.src[5] = wg2;  ta.dst[5] = (__half*)p_wg2;
    ta.src[6] = wout; ta.dst[6] = (__half*)p_wout;
    long tern_chunks = 4L * (DIM*DIM/8) + 3L * (HID*DIM/8);
    tern_all_kernel<<<(unsigned)((tern_chunks + T - 1) / T), T>>>(ta);

    // 2) x -> hi/lo fp16
    split_kernel<<<(nBD/8 + T - 1)/T, T>>>((const float4*)x, (uint4*)p_xhi, (uint4*)p_xlo, nBD/8);

    dim3 gridD(DIM / BN, BATCH / BM);   // (8, 32)
    dim3 gridH(HID / BN, BATCH / BM);   // (32, 32)

    // 3) F, C, G
    gemm_hmma<<<gridD, 512, GEMM_SMEM>>>((__half*)p_xhi, (__half*)p_xlo,
                                         (__half*)p_wf, bf_, (float*)p_F, BATCH, DIM, DIM, 1.0f);
    gemm_hmma<<<gridD, 512, GEMM_SMEM>>>((__half*)p_xhi, (__half*)p_xlo,
                                         (__half*)p_wc, bc,  (float*)p_C, BATCH, DIM, DIM, 1.0f);
    gemm_hmma<<<gridD, 512, GEMM_SMEM>>>((__half*)p_xhi, (__half*)p_xlo,
                                         (__half*)p_wg, bg,  (float*)p_G, BATCH, DIM, DIM, 1.0f);

    // 4) gate fuse -> t hi/lo
    mlgru_ew_kernel<<<(nBD/4 + T - 1)/T, T>>>(nBD/4);

    // 5) O = t @ Wo^T + bo ; O -> hi/lo
    gemm_hmma<<<gridD, 512, GEMM_SMEM>>>((__half*)p_thi, (__half*)p_tlo,
                                         (__half*)p_wo, bo, (float*)p_O, BATCH, DIM, DIM, 1.0f);
    split_kernel<<<(nBD/8 + T - 1)/T, T>>>((const float4*)p_O, (uint4*)p_ohi, (uint4*)p_olo, nBD/8);

    // 6) GG, U  (N=8192, K=2048)
    gemm_hmma<<<gridH, 512, GEMM_SMEM>>>((__half*)p_ohi, (__half*)p_olo,
                                         (__half*)p_wg2, bg2, (float*)p_GG, BATCH, HID, DIM, 1.0f);
    gemm_hmma<<<gridH, 512, GEMM_SMEM>>>((__half*)p_ohi, (__half*)p_olo,
                                         (__half*)p_wu,  bu,  (float*)p_U,  BATCH, HID, DIM, 1.0f);

    // 7) s = sigmoid(GG)*silu(U) / SSCALE  (hi/lo, overflow-safe)
    glu_ew_kernel<<<(nBH/4 + T - 1)/T, T>>>(nBH/4);

    // 8) out = SSCALE * (s/SSCALE) @ Wout^T + bout   (K=8192)
    gemm_hmma<<<gridD, 512, GEMM_SMEM>>>((__half*)p_shi, (__half*)p_slo,
                                         (__half*)p_wout, bout, out, BATCH, DIM, HID, SSCALE);
}

// round 7
// speedup vs baseline: 1.2160x; 1.2160x over previous
#include <cuda_runtime.h>
#include <cuda_fp16.h>
#include <cstdint>

#define DIM   2048
#define HID   8192
#define BATCH 4096

// ---------------- GEMM tiling ----------------
#define BM 128
#define BN 256
#define BK 32                      // fp16 K elements per stage (per hi/lo pass)
#define SROW 80                    // 64B data + 16B pad per row
#define STAGES 3
#define A_STG (BM * SROW)          // 10240 B  (one of Ahi / Alo)
#define B_STG (BN * SROW)          // 20480 B
#define STG   (2 * A_STG + B_STG)  // 40960 B : [Ahi | Alo | B]
#define GEMM_SMEM (STAGES * STG)   // 122880 B

// s is scaled by 1/SSCALE before the final GEMM to avoid fp16 overflow
#define SSCALE 64.0f

// ---------------- device scratch ----------------
__device__ __align__(256) __half g_wf [DIM*DIM];
__device__ __align__(256) __half g_wc [DIM*DIM];
__device__ __align__(256) __half g_wg [DIM*DIM];
__device__ __align__(256) __half g_wo [DIM*DIM];
__device__ __align__(256) __half g_wu [HID*DIM];
__device__ __align__(256) __half g_wg2[HID*DIM];
__device__ __align__(256) __half g_wout[DIM*HID];

__device__ __align__(256) __half g_xhi[BATCH*DIM], g_xlo[BATCH*DIM];
__device__ __align__(256) float g_F[BATCH*DIM], g_C[BATCH*DIM], g_G[BATCH*DIM];
__device__ __align__(256) __half g_thi[BATCH*DIM], g_tlo[BATCH*DIM];
__device__ __align__(256) float g_O[BATCH*DIM];
__device__ __align__(256) __half g_ohi[BATCH*DIM], g_olo[BATCH*DIM];
__device__ __align__(256) float g_GG[BATCH*HID], g_U[BATCH*HID];
__device__ __align__(256) __half g_shi[BATCH*HID], g_slo[BATCH*HID];

// ---------------- PTX helpers ----------------
__device__ __forceinline__ uint32_t smem_u32(const void* p) {
    uint32_t a;
    asm("{ .reg .u64 t; cvta.to.shared.u64 t, %1; cvt.u32.u64 %0, t; }" : "=r"(a) : "l"(p));
    return a;
}
__device__ __forceinline__ void cp_async16(uint32_t s, const void* g) {
    asm volatile("cp.async.cg.shared.global [%0], [%1], 16;\n" :: "r"(s), "l"(g) : "memory");
}
__device__ __forceinline__ void cp_commit() {
    asm volatile("cp.async.commit_group;\n" ::: "memory");
}
__device__ __forceinline__ void ldsm_x4(uint32_t* r, uint32_t a) {
    asm volatile("ldmatrix.sync.aligned.m8n8.x4.shared.b16 {%0,%1,%2,%3}, [%4];\n"
                 : "=r"(r[0]), "=r"(r[1]), "=r"(r[2]), "=r"(r[3]) : "r"(a));
}
__device__ __forceinline__ void mma_f16(float* c, const uint32_t* a, const uint32_t* b) {
    asm volatile(
        "mma.sync.aligned.m16n8k16.row.col.f32.f16.f16.f32 "
        "{%0,%1,%2,%3}, {%4,%5,%6,%7}, {%8,%9}, {%0,%1,%2,%3};\n"
        : "+f"(c[0]), "+f"(c[1]), "+f"(c[2]), "+f"(c[3])
        : "r"(a[0]), "r"(a[1]), "r"(a[2]), "r"(a[3]), "r"(b[0]), "r"(b[1]));
}

// ---------------- elementwise ----------------
__device__ __forceinline__ float sigmoidf_(float v) { return 1.0f / (1.0f + expf(-v)); }

struct TernArgs {
    const float* src[7];
    __half*      dst[7];
};

// One kernel ternarizes all 7 weight matrices.
__global__ void tern_all_kernel(TernArgs args) {
    const int ndd = DIM * DIM / 8;
    const int nhd = HID * DIM / 8;
    long i = (long)blockIdx.x * blockDim.x + threadIdx.x;
    long total = 4L * ndd + 3L * nhd;
    if (i >= total) return;
    int seg; long off;
    if (i < 4L * ndd) { seg = (int)(i / ndd); off = i - (long)seg * ndd; }
    else { long j = i - 4L * ndd; seg = 4 + (int)(j / nhd); off = j - (long)(seg - 4) * nhd; }
    const float4* s = (const float4*)args.src[seg];
    uint4* d = (uint4*)args.dst[seg];
    float4 a = s[2*off], b = s[2*off+1];
    float v[8] = {a.x, a.y, a.z, a.w, b.x, b.y, b.z, b.w};
    union { uint4 u; __half h[8]; } r;
    #pragma unroll
    for (int j = 0; j < 8; j++) {
        float t = (fabsf(v[j]) < 0.33f) ? 0.0f : (v[j] > 0.0f ? 1.0f : -1.0f);
        r.h[j] = __float2half_rn(t);
    }
    d[off] = r.u;
}

// fp32 -> (hi, lo) fp16 pair
__global__ void split_kernel(const float4* __restrict__ v,
                             uint4* __restrict__ hi, uint4* __restrict__ lo, int n8) {
    int i = blockIdx.x * blockDim.x + threadIdx.x;
    if (i >= n8) return;
    float4 a = v[2*i], b = v[2*i+1];
    float x[8] = {a.x, a.y, a.z, a.w, b.x, b.y, b.z, b.w};
    union { uint4 u; __half h[8]; } rh, rl;
    #pragma unroll
    for (int j = 0; j < 8; j++) {
        __half h = __float2half_rn(x[j]);
        rh.h[j] = h;
        rl.h[j] = __float2half_rn(x[j] - __half2float(h));
    }
    hi[i] = rh.u; lo[i] = rl.u;
}

__global__ void mlgru_ew_kernel(int n4) {
    int i = blockIdx.x * blockDim.x + threadIdx.x;
    if (i >= n4) return;
    float4 f4 = ((const float4*)g_F)[i];
    float4 c4 = ((const float4*)g_C)[i];
    float4 g4 = ((const float4*)g_G)[i];
    float fv[4] = {f4.x, f4.y, f4.z, f4.w};
    float cv[4] = {c4.x, c4.y, c4.z, c4.w};
    float gv[4] = {g4.x, g4.y, g4.z, g4.w};
    union { uint2 u; __half h[4]; } rh, rl;
    #pragma unroll
    for (int j = 0; j < 4; j++) {
        float f = sigmoidf_(fv[j]);
        float c = cv[j] * sigmoidf_(cv[j]);
        float g = sigmoidf_(gv[j]);
        float t = g * (1.0f - f) * c;
        __half h = __float2half_rn(t);
        rh.h[j] = h;
        rl.h[j] = __float2half_rn(t - __half2float(h));
    }
    ((uint2*)g_thi)[i] = rh.u;
    ((uint2*)g_tlo)[i] = rl.u;
}

// s = sigmoid(GG)*silu(U) / SSCALE, hi/lo fp16
__global__ void glu_ew_kernel(int n4) {
    int i = blockIdx.x * blockDim.x + threadIdx.x;
    if (i >= n4) return;
    float4 gg4 = ((const float4*)g_GG)[i];
    float4 u4  = ((const float4*)g_U)[i];
    float ggv[4] = {gg4.x, gg4.y, gg4.z, gg4.w};
    float uv[4]  = {u4.x, u4.y, u4.z, u4.w};
    union { uint2 u; __half h[4]; } rh, rl;
    #pragma unroll
    for (int j = 0; j < 4; j++) {
        float gg = sigmoidf_(ggv[j]);
        float u  = uv[j] * sigmoidf_(uv[j]);
        float s  = gg * u * (1.0f / SSCALE);
        __half h = __float2half_rn(s);
        rh.h[j] = h;
        rl.h[j] = __float2half_rn(s - __half2float(h));
    }
    ((uint2*)g_shi)[i] = rh.u;
    ((uint2*)g_slo)[i] = rl.u;
}

// ---------------- HMMA GEMM --------------------------------------------------
// out[M,N] = alpha * ((Ahi + Alo)[M,K] @ W[N,K]^T) + bias   (fp32 out)
// CTA 128x256, 512 threads, warp tile 32x64.
// Per K-tile stage holds {Ahi, Alo, B}; B fragments are reused for both the
// hi and lo MMA -> half the B smem/global traffic, 32 MMAs per warp per ks.
// ks order staggered by warp parity to de-phase ldsm vs mma across warps.
__global__ __launch_bounds__(512, 1) void gemm_hmma(
    const __half* __restrict__ Ahi,
    const __half* __restrict__ Alo,
    const __half* __restrict__ W,
    const float* __restrict__ bias,
    float* __restrict__ out,
    int M, int N, int K, float alpha)
{
    extern __shared__ __align__(16) unsigned char smem[];

    const int tid  = threadIdx.x;
    const int lane = tid & 31;
    const int warp = tid >> 5;      // 0..15
    const int wm   = warp & 3;      // M band: 32 rows
    const int wn   = warp >> 2;     // N band: 64 cols
    const long bM  = (long)blockIdx.y * BM;
    const long bN  = (long)blockIdx.x * BN;

    const int KT = K / BK;          // K-tiles (each covers hi AND lo)

    float acc[2][8][4];
    #pragma unroll
    for (int i = 0; i < 2; i++)
        #pragma unroll
        for (int j = 0; j < 8; j++)
            #pragma unroll
            for (int k = 0; k < 4; k++) acc[i][j][k] = 0.0f;

    // chunks per stage: Ahi 512, Alo 512, B 1024  (16B each) = 2048
    auto issue_tile = [&](int it_, int stg_) {
        long kk = (long)it_ * BK;
        unsigned char* s = smem + stg_ * STG;
        #pragma unroll
        for (int c = tid; c < 2048; c += 512) {
            const __half* g;
            uint32_t dst;
            if (c < 512) {                    // Ahi
                int row = c >> 2, kc = c & 3;
                g = Ahi + (bM + row) * (long)K + kk + kc * 8;
                dst = smem_u32(s + row * SROW + kc * 16);
            } else if (c < 1024) {            // Alo
                int cc = c - 512;
                int row = cc >> 2, kc = cc & 3;
                g = Alo + (bM + row) * (long)K + kk + kc * 8;
                dst = smem_u32(s + A_STG + row * SROW + kc * 16);
            } else {                          // B
                int cc = c - 1024;
                int row = cc >> 2, kc = cc & 3;
                g = W + (bN + row) * (long)K + kk + kc * 8;
                dst = smem_u32(s + 2 * A_STG + row * SROW + kc * 16);
            }
            cp_async16(dst, g);
        }
        cp_commit();
    };

    issue_tile(0, 0);
    if (KT > 1) issue_tile(1, 1);

    const int g1 = (lane >> 3) & 1;
    const int g2 = lane >> 4;
    const int r8 = lane & 7;
    const int par = warp & 1;       // ks stagger

    int stg = 0;                    // stage of iteration `it`
    for (int it = 0; it < KT; it++) {
        if (it + 1 < KT) asm volatile("cp.async.wait_group 1;\n" ::: "memory");
        else             asm volatile("cp.async.wait_group 0;\n" ::: "memory");
        __syncthreads();
        // stage written by it+2 = stage of it-1, whose reads finished before this sync
        int nstg = stg + 1 == STAGES ? 0 : stg + 1;
        int wstg = nstg + 1 == STAGES ? 0 : nstg + 1;
        if (it + 2 < KT) issue_tile(it + 2, wstg);

        unsigned char* sAh = smem + stg * STG;
        unsigned char* sAl = sAh + A_STG;
        unsigned char* sB  = sAh + 2 * A_STG;

        #pragma unroll
        for (int ks = 0; ks < 2; ks++) {
            int kss = ks ^ par;
            uint32_t aH[2][4], aL[2][4], bF[8][2];
            #pragma unroll
            for (int mi = 0; mi < 2; mi++) {
                int r = wm * 32 + mi * 16 + g1 * 8 + r8;
                int c = kss * 2 + g2;
                ldsm_x4(aH[mi], smem_u32(sAh + r * SROW + c * 16));
                ldsm_x4(aL[mi], smem_u32(sAl + r * SROW + c * 16));
            }
            #pragma unroll
            for (int nb = 0; nb < 4; nb++) {
                int r = wn * 64 + nb * 16 + g2 * 8 + r8;
                int c = kss * 2 + g1;
                uint32_t t[4];
                ldsm_x4(t, smem_u32(sB + r * SROW + c * 16));
                bF[nb * 2 + 0][0] = t[0]; bF[nb * 2 + 0][1] = t[1];
                bF[nb * 2 + 1][0] = t[2]; bF[nb * 2 + 1][1] = t[3];
            }
            #pragma unroll
            for (int mi = 0; mi < 2; mi++)
                #pragma unroll
                for (int nj = 0; nj < 8; nj++) {
                    mma_f16(acc[mi][nj], aH[mi], bF[nj]);
                    mma_f16(acc[mi][nj], aL[mi], bF[nj]);
                }
        }
        stg = nstg;
    }

    // epilogue: alpha*acc + bias, fp32 store
    const int cg = lane >> 2, tg = lane & 3;
    #pragma unroll
    for (int mi = 0; mi < 2; mi++) {
        #pragma unroll
        for (int nj = 0; nj < 8; nj++) {
            long row = bM + wm * 32 + mi * 16 + cg;
            long col = bN + wn * 64 + nj * 8 + tg * 2;
            float b0 = bias[col], b1 = bias[col + 1];
            float2 v0 = make_float2(fmaf(alpha, acc[mi][nj][0], b0),
                                    fmaf(alpha, acc[mi][nj][1], b1));
            float2 v1 = make_float2(fmaf(alpha, acc[mi][nj][2], b0),
                                    fmaf(alpha, acc[mi][nj][3], b1));
            *reinterpret_cast<float2*>(out + row * (long)N + col)       = v0;
            *reinterpret_cast<float2*>(out + (row + 8) * (long)N + col) = v1;
        }
    }
}

// ---------------- host launcher ----------------
extern "C" void kernel_launch(void* const* d_in, const int* in_sizes, int n_in,
                              void* d_out, int out_size)
{
    (void)in_sizes; (void)n_in; (void)out_size;
    const float* x    = (const float*)d_in[0];
    const float* wf   = (const float*)d_in[1];
    const float* bf_  = (const float*)d_in[2];
    const float* wc   = (const float*)d_in[3];
    const float* bc   = (const float*)d_in[4];
    const float* wg   = (const float*)d_in[5];
    const float* bg   = (const float*)d_in[6];
    const float* wo   = (const float*)d_in[7];
    const float* bo   = (const float*)d_in[8];
    const float* wu   = (const float*)d_in[9];
    const float* bu   = (const float*)d_in[10];
    const float* wg2  = (const float*)d_in[11];
    const float* bg2  = (const float*)d_in[12];
    const float* wout = (const float*)d_in[13];
    const float* bout = (const float*)d_in[14];
    float* out = (float*)d_out;

    cudaFuncSetAttribute(gemm_hmma, cudaFuncAttributeMaxDynamicSharedMemorySize, GEMM_SMEM);

    void *p_wf, *p_wc, *p_wg, *p_wo, *p_wu, *p_wg2, *p_wout;
    void *p_xhi, *p_xlo, *p_F, *p_C, *p_G, *p_thi, *p_tlo;
    void *p_O, *p_ohi, *p_olo, *p_GG, *p_U, *p_shi, *p_slo;
    cudaGetSymbolAddress(&p_wf, g_wf);     cudaGetSymbolAddress(&p_wc, g_wc);
    cudaGetSymbolAddress(&p_wg, g_wg);     cudaGetSymbolAddress(&p_wo, g_wo);
    cudaGetSymbolAddress(&p_wu, g_wu);     cudaGetSymbolAddress(&p_wg2, g_wg2);
    cudaGetSymbolAddress(&p_wout, g_wout);
    cudaGetSymbolAddress(&p_xhi, g_xhi);   cudaGetSymbolAddress(&p_xlo, g_xlo);
    cudaGetSymbolAddress(&p_F, g_F);       cudaGetSymbolAddress(&p_C, g_C);
    cudaGetSymbolAddress(&p_G, g_G);
    cudaGetSymbolAddress(&p_thi, g_thi);   cudaGetSymbolAddress(&p_tlo, g_tlo);
    cudaGetSymbolAddress(&p_O, g_O);
    cudaGetSymbolAddress(&p_ohi, g_ohi);   cudaGetSymbolAddress(&p_olo, g_olo);
    cudaGetSymbolAddress(&p_GG, g_GG);     cudaGetSymbolAddress(&p_U, g_U);
    cudaGetSymbolAddress(&p_shi, g_shi);   cudaGetSymbolAddress(&p_slo, g_slo);

    const int T = 256;
    const int nBD = BATCH * DIM, nBH = BATCH * HID;

    // 1) all ternarizations in ONE launch
    TernArgs ta;
    ta.src[0] = wf;   ta.dst[0] = (__half*)p_wf;
    ta.src[1] = wc;   ta.dst[1] = (__half*)p_wc;
    ta.src[2] = wg;   ta.dst[2] = (__half*)p_wg;
    ta.src[3] = wo;   ta.dst[3] = (__half*)p_wo;
    ta.src[4] = wu;   ta.dst[4] = (__half*)p_wu;
    ta.src[5] = wg2;  ta.dst[5] = (__half*)p_wg2;
    ta.src[6] = wout; ta.dst[6] = (__half*)p_wout;
    long tern_chunks = 4L * (DIM*DIM/8) + 3L * (HID*DIM/8);
    tern_all_kernel<<<(unsigned)((tern_chunks + T - 1) / T), T>>>(ta);

    // 2) x -> hi/lo fp16
    split_kernel<<<(nBD/8 + T - 1)/T, T>>>((const float4*)x, (uint4*)p_xhi, (uint4*)p_xlo, nBD/8);

    dim3 gridD(DIM / BN, BATCH / BM);   // (8, 32)
    dim3 gridH(HID / BN, BATCH / BM);   // (32, 32)

    // 3) F, C, G
    gemm_hmma<<<gridD, 512, GEMM_SMEM>>>((__half*)p_xhi, (__half*)p_xlo,
                                         (__half*)p_wf, bf_, (float*)p_F, BATCH, DIM, DIM, 1.0f);
    gemm_hmma<<<gridD, 512, GEMM_SMEM>>>((__half*)p_xhi, (__half*)p_xlo,
                                         (__half*)p_wc, bc,  (float*)p_C, BATCH, DIM, DIM, 1.0f);
    gemm_hmma<<<gridD, 512, GEMM_SMEM>>>((__half*)p_xhi, (__half*)p_xlo,
                                         (__half*)p_wg, bg,  (float*)p_G, BATCH, DIM, DIM, 1.0f);

    // 4) gate fuse -> t hi/lo
    mlgru_ew_kernel<<<(nBD/4 + T - 1)/T, T>>>(nBD/4);

    // 5) O = t @ Wo^T + bo ; O -> hi/lo
    gemm_hmma<<<gridD, 512, GEMM_SMEM>>>((__half*)p_thi, (__half*)p_tlo,
                                         (__half*)p_wo, bo, (float*)p_O, BATCH, DIM, DIM, 1.0f);
    split_kernel<<<(nBD/8 + T - 1)/T, T>>>((const float4*)p_O, (uint4*)p_ohi, (uint4*)p_olo, nBD/8);

    // 6) GG, U  (N=8192, K=2048)
    gemm_hmma<<<gridH, 512, GEMM_SMEM>>>((__half*)p_ohi, (__half*)p_olo,
                                         (__half*)p_wg2, bg2, (float*)p_GG, BATCH, HID, DIM, 1.0f);
    gemm_hmma<<<gridH, 512, GEMM_SMEM>>>((__half*)p_ohi, (__half*)p_olo,
                                         (__half*)p_wu,  bu,  (float*)p_U,  BATCH, HID, DIM, 1.0f);

    // 7) s = sigmoid(GG)*silu(U) / SSCALE  (hi/lo, overflow-safe)
    glu_ew_kernel<<<(nBH/4 + T - 1)/T, T>>>(nBH/4);

    // 8) out = SSCALE * (s/SSCALE) @ Wout^T + bout   (K=8192)
    gemm_hmma<<<gridD, 512, GEMM_SMEM>>>((__half*)p_shi, (__half*)p_slo,
                                         (__half*)p_wout, bout, out, BATCH, DIM, HID, SSCALE);
}

// round 8
// speedup vs baseline: 1.2725x; 1.0465x over previous
#include <cuda_runtime.h>
#include <cuda_fp16.h>
#include <cstdint>

#define DIM   2048
#define HID   8192
#define BATCH 4096

// ---------------- GEMM tiling ----------------
#define BM 128
#define BN 128
#define BK 32                      // fp16 K elements per stage (per hi/lo pass)
#define SROW 80                    // 64B data + 16B pad per row
#define STAGES 3
#define A_STG (BM * SROW)          // 10240 B (one of Ahi / Alo)
#define B_STG (BN * SROW)          // 10240 B
#define STG   (2 * A_STG + B_STG)  // 30720 B : [Ahi | Alo | B]
#define GEMM_SMEM (STAGES * STG)   // 92160 B  -> 2 CTAs/SM
#define CHUNKS 1536                // 16B cp.async chunks per stage

// s is scaled by 1/SSCALE before the final GEMM to avoid fp16 overflow
#define SSCALE 64.0f

// ---------------- device scratch ----------------
__device__ __align__(256) __half g_wf [DIM*DIM];
__device__ __align__(256) __half g_wc [DIM*DIM];
__device__ __align__(256) __half g_wg [DIM*DIM];
__device__ __align__(256) __half g_wo [DIM*DIM];
__device__ __align__(256) __half g_wu [HID*DIM];
__device__ __align__(256) __half g_wg2[HID*DIM];
__device__ __align__(256) __half g_wout[DIM*HID];

__device__ __align__(256) __half g_xhi[BATCH*DIM], g_xlo[BATCH*DIM];
__device__ __align__(256) float g_F[BATCH*DIM], g_C[BATCH*DIM], g_G[BATCH*DIM];
__device__ __align__(256) __half g_thi[BATCH*DIM], g_tlo[BATCH*DIM];
__device__ __align__(256) float g_O[BATCH*DIM];
__device__ __align__(256) __half g_ohi[BATCH*DIM], g_olo[BATCH*DIM];
__device__ __align__(256) float g_GG[BATCH*HID], g_U[BATCH*HID];
__device__ __align__(256) __half g_shi[BATCH*HID], g_slo[BATCH*HID];

// ---------------- PTX helpers ----------------
__device__ __forceinline__ uint32_t smem_u32(const void* p) {
    uint32_t a;
    asm("{ .reg .u64 t; cvta.to.shared.u64 t, %1; cvt.u32.u64 %0, t; }" : "=r"(a) : "l"(p));
    return a;
}
__device__ __forceinline__ void cp_async16(uint32_t s, const void* g) {
    asm volatile("cp.async.cg.shared.global [%0], [%1], 16;\n" :: "r"(s), "l"(g) : "memory");
}
__device__ __forceinline__ void cp_commit() {
    asm volatile("cp.async.commit_group;\n" ::: "memory");
}
__device__ __forceinline__ void ldsm_x4(uint32_t* r, uint32_t a) {
    asm volatile("ldmatrix.sync.aligned.m8n8.x4.shared.b16 {%0,%1,%2,%3}, [%4];\n"
                 : "=r"(r[0]), "=r"(r[1]), "=r"(r[2]), "=r"(r[3]) : "r"(a));
}
__device__ __forceinline__ void mma_f16(float* c, const uint32_t* a, const uint32_t* b) {
    asm volatile(
        "mma.sync.aligned.m16n8k16.row.col.f32.f16.f16.f32 "
        "{%0,%1,%2,%3}, {%4,%5,%6,%7}, {%8,%9}, {%0,%1,%2,%3};\n"
        : "+f"(c[0]), "+f"(c[1]), "+f"(c[2]), "+f"(c[3])
        : "r"(a[0]), "r"(a[1]), "r"(a[2]), "r"(a[3]), "r"(b[0]), "r"(b[1]));
}

// ---------------- elementwise ----------------
__device__ __forceinline__ float sigmoidf_(float v) { return 1.0f / (1.0f + expf(-v)); }

struct TernArgs {
    const float* src[7];
    __half*      dst[7];
};

// One kernel ternarizes all 7 weight matrices.
__global__ void tern_all_kernel(TernArgs args) {
    const int ndd = DIM * DIM / 8;
    const int nhd = HID * DIM / 8;
    long i = (long)blockIdx.x * blockDim.x + threadIdx.x;
    long total = 4L * ndd + 3L * nhd;
    if (i >= total) return;
    int seg; long off;
    if (i < 4L * ndd) { seg = (int)(i / ndd); off = i - (long)seg * ndd; }
    else { long j = i - 4L * ndd; seg = 4 + (int)(j / nhd); off = j - (long)(seg - 4) * nhd; }
    const float4* s = (const float4*)args.src[seg];
    uint4* d = (uint4*)args.dst[seg];
    float4 a = s[2*off], b = s[2*off+1];
    float v[8] = {a.x, a.y, a.z, a.w, b.x, b.y, b.z, b.w};
    union { uint4 u; __half h[8]; } r;
    #pragma unroll
    for (int j = 0; j < 8; j++) {
        float t = (fabsf(v[j]) < 0.33f) ? 0.0f : (v[j] > 0.0f ? 1.0f : -1.0f);
        r.h[j] = __float2half_rn(t);
    }
    d[off] = r.u;
}

// fp32 -> (hi, lo) fp16 pair
__global__ void split_kernel(const float4* __restrict__ v,
                             uint4* __restrict__ hi, uint4* __restrict__ lo, int n8) {
    int i = blockIdx.x * blockDim.x + threadIdx.x;
    if (i >= n8) return;
    float4 a = v[2*i], b = v[2*i+1];
    float x[8] = {a.x, a.y, a.z, a.w, b.x, b.y, b.z, b.w};
    union { uint4 u; __half h[8]; } rh, rl;
    #pragma unroll
    for (int j = 0; j < 8; j++) {
        __half h = __float2half_rn(x[j]);
        rh.h[j] = h;
        rl.h[j] = __float2half_rn(x[j] - __half2float(h));
    }
    hi[i] = rh.u; lo[i] = rl.u;
}

__global__ void mlgru_ew_kernel(int n4) {
    int i = blockIdx.x * blockDim.x + threadIdx.x;
    if (i >= n4) return;
    float4 f4 = ((const float4*)g_F)[i];
    float4 c4 = ((const float4*)g_C)[i];
    float4 g4 = ((const float4*)g_G)[i];
    float fv[4] = {f4.x, f4.y, f4.z, f4.w};
    float cv[4] = {c4.x, c4.y, c4.z, c4.w};
    float gv[4] = {g4.x, g4.y, g4.z, g4.w};
    union { uint2 u; __half h[4]; } rh, rl;
    #pragma unroll
    for (int j = 0; j < 4; j++) {
        float f = sigmoidf_(fv[j]);
        float c = cv[j] * sigmoidf_(cv[j]);
        float g = sigmoidf_(gv[j]);
        float t = g * (1.0f - f) * c;
        __half h = __float2half_rn(t);
        rh.h[j] = h;
        rl.h[j] = __float2half_rn(t - __half2float(h));
    }
    ((uint2*)g_thi)[i] = rh.u;
    ((uint2*)g_tlo)[i] = rl.u;
}

// s = sigmoid(GG)*silu(U) / SSCALE, hi/lo fp16
__global__ void glu_ew_kernel(int n4) {
    int i = blockIdx.x * blockDim.x + threadIdx.x;
    if (i >= n4) return;
    float4 gg4 = ((const float4*)g_GG)[i];
    float4 u4  = ((const float4*)g_U)[i];
    float ggv[4] = {gg4.x, gg4.y, gg4.z, gg4.w};
    float uv[4]  = {u4.x, u4.y, u4.z, u4.w};
    union { uint2 u; __half h[4]; } rh, rl;
    #pragma unroll
    for (int j = 0; j < 4; j++) {
        float gg = sigmoidf_(ggv[j]);
        float u  = uv[j] * sigmoidf_(uv[j]);
        float s  = gg * u * (1.0f / SSCALE);
        __half h = __float2half_rn(s);
        rh.h[j] = h;
        rl.h[j] = __float2half_rn(s - __half2float(h));
    }
    ((uint2*)g_shi)[i] = rh.u;
    ((uint2*)g_slo)[i] = rl.u;
}

// ---------------- HMMA GEMM --------------------------------------------------
// out[M,N] = alpha * ((Ahi + Alo)[M,K] @ W[N,K]^T) + bias   (fp32 out)
// CTA tile 128x128, 256 threads, warp tile 32x64 (4x2), 2 CTAs per SM.
// Stage holds {Ahi, Alo, B}; B fragments reused for hi and lo MMAs.
__global__ __launch_bounds__(256, 2) void gemm_hmma(
    const __half* __restrict__ Ahi,
    const __half* __restrict__ Alo,
    const __half* __restrict__ W,
    const float* __restrict__ bias,
    float* __restrict__ out,
    int M, int N, int K, float alpha)
{
    extern __shared__ __align__(16) unsigned char smem[];

    const int tid  = threadIdx.x;
    const int lane = tid & 31;
    const int warp = tid >> 5;      // 0..7
    const int wm   = warp & 3;      // M band: 32 rows
    const int wn   = warp >> 2;     // N band: 64 cols
    const long bM  = (long)blockIdx.y * BM;
    const long bN  = (long)blockIdx.x * BN;

    const int KT = K / BK;          // K-tiles (each covers hi AND lo)

    float acc[2][8][4];
    #pragma unroll
    for (int i = 0; i < 2; i++)
        #pragma unroll
        for (int j = 0; j < 8; j++)
            #pragma unroll
            for (int k = 0; k < 4; k++) acc[i][j][k] = 0.0f;

    // chunks per stage: Ahi 512, Alo 512, B 512 (16B each) = 1536
    auto issue_tile = [&](int it_, int stg_) {
        long kk = (long)it_ * BK;
        unsigned char* s = smem + stg_ * STG;
        #pragma unroll
        for (int c = tid; c < CHUNKS; c += 256) {
            const __half* g;
            uint32_t dst;
            if (c < 512) {                    // Ahi
                int row = c >> 2, kc = c & 3;
                g = Ahi + (bM + row) * (long)K + kk + kc * 8;
                dst = smem_u32(s + row * SROW + kc * 16);
            } else if (c < 1024) {            // Alo
                int cc = c - 512;
                int row = cc >> 2, kc = cc & 3;
                g = Alo + (bM + row) * (long)K + kk + kc * 8;
                dst = smem_u32(s + A_STG + row * SROW + kc * 16);
            } else {                          // B
                int cc = c - 1024;
                int row = cc >> 2, kc = cc & 3;
                g = W + (bN + row) * (long)K + kk + kc * 8;
                dst = smem_u32(s + 2 * A_STG + row * SROW + kc * 16);
            }
            cp_async16(dst, g);
        }
        cp_commit();
    };

    issue_tile(0, 0);
    if (KT > 1) issue_tile(1, 1);

    const int g1 = (lane >> 3) & 1;
    const int g2 = lane >> 4;
    const int r8 = lane & 7;
    const int par = warp & 1;       // ks stagger

    int stg = 0;                    // stage of iteration `it`
    for (int it = 0; it < KT; it++) {
        if (it + 1 < KT) asm volatile("cp.async.wait_group 1;\n" ::: "memory");
        else             asm volatile("cp.async.wait_group 0;\n" ::: "memory");
        __syncthreads();
        int nstg = stg + 1 == STAGES ? 0 : stg + 1;
        int wstg = nstg + 1 == STAGES ? 0 : nstg + 1;
        if (it + 2 < KT) issue_tile(it + 2, wstg);

        unsigned char* sAh = smem + stg * STG;
        unsigned char* sAl = sAh + A_STG;
        unsigned char* sB  = sAh + 2 * A_STG;

        #pragma unroll
        for (int ks = 0; ks < 2; ks++) {
            int kss = ks ^ par;
            uint32_t aH[2][4], aL[2][4], bF[8][2];
            #pragma unroll
            for (int mi = 0; mi < 2; mi++) {
                int r = wm * 32 + mi * 16 + g1 * 8 + r8;
                int c = kss * 2 + g2;
                ldsm_x4(aH[mi], smem_u32(sAh + r * SROW + c * 16));
                ldsm_x4(aL[mi], smem_u32(sAl + r * SROW + c * 16));
            }
            #pragma unroll
            for (int nb = 0; nb < 4; nb++) {
                int r = wn * 64 + nb * 16 + g2 * 8 + r8;
                int c = kss * 2 + g1;
                uint32_t t[4];
                ldsm_x4(t, smem_u32(sB + r * SROW + c * 16));
                bF[nb * 2 + 0][0] = t[0]; bF[nb * 2 + 0][1] = t[1];
                bF[nb * 2 + 1][0] = t[2]; bF[nb * 2 + 1][1] = t[3];
            }
            #pragma unroll
            for (int mi = 0; mi < 2; mi++)
                #pragma unroll
                for (int nj = 0; nj < 8; nj++) {
                    mma_f16(acc[mi][nj], aH[mi], bF[nj]);
                    mma_f16(acc[mi][nj], aL[mi], bF[nj]);
                }
        }
        stg = nstg;
    }

    // epilogue: alpha*acc + bias, fp32 store
    const int cg = lane >> 2, tg = lane & 3;
    #pragma unroll
    for (int mi = 0; mi < 2; mi++) {
        #pragma unroll
        for (int nj = 0; nj < 8; nj++) {
            long row = bM + wm * 32 + mi * 16 + cg;
            long col = bN + wn * 64 + nj * 8 + tg * 2;
            float b0 = bias[col], b1 = bias[col + 1];
            float2 v0 = make_float2(fmaf(alpha, acc[mi][nj][0], b0),
                                    fmaf(alpha, acc[mi][nj][1], b1));
            float2 v1 = make_float2(fmaf(alpha, acc[mi][nj][2], b0),
                                    fmaf(alpha, acc[mi][nj][3], b1));
            *reinterpret_cast<float2*>(out + row * (long)N + col)       = v0;
            *reinterpret_cast<float2*>(out + (row + 8) * (long)N + col) = v1;
        }
    }
}

// ---------------- host launcher ----------------
extern "C" void kernel_launch(void* const* d_in, const int* in_sizes, int n_in,
                              void* d_out, int out_size)
{
    (void)in_sizes; (void)n_in; (void)out_size;
    const float* x    = (const float*)d_in[0];
    const float* wf   = (const float*)d_in[1];
    const float* bf_  = (const float*)d_in[2];
    const float* wc   = (const float*)d_in[3];
    const float* bc   = (const float*)d_in[4];
    const float* wg   = (const float*)d_in[5];
    const float* bg   = (const float*)d_in[6];
    const float* wo   = (const float*)d_in[7];
    const float* bo   = (const float*)d_in[8];
    const float* wu   = (const float*)d_in[9];
    const float* bu   = (const float*)d_in[10];
    const float* wg2  = (const float*)d_in[11];
    const float* bg2  = (const float*)d_in[12];
    const float* wout = (const float*)d_in[13];
    const float* bout = (const float*)d_in[14];
    float* out = (float*)d_out;

    cudaFuncSetAttribute(gemm_hmma, cudaFuncAttributeMaxDynamicSharedMemorySize, GEMM_SMEM);

    void *p_wf, *p_wc, *p_wg, *p_wo, *p_wu, *p_wg2, *p_wout;
    void *p_xhi, *p_xlo, *p_F, *p_C, *p_G, *p_thi, *p_tlo;
    void *p_O, *p_ohi, *p_olo, *p_GG, *p_U, *p_shi, *p_slo;
    cudaGetSymbolAddress(&p_wf, g_wf);     cudaGetSymbolAddress(&p_wc, g_wc);
    cudaGetSymbolAddress(&p_wg, g_wg);     cudaGetSymbolAddress(&p_wo, g_wo);
    cudaGetSymbolAddress(&p_wu, g_wu);     cudaGetSymbolAddress(&p_wg2, g_wg2);
    cudaGetSymbolAddress(&p_wout, g_wout);
    cudaGetSymbolAddress(&p_xhi, g_xhi);   cudaGetSymbolAddress(&p_xlo, g_xlo);
    cudaGetSymbolAddress(&p_F, g_F);       cudaGetSymbolAddress(&p_C, g_C);
    cudaGetSymbolAddress(&p_G, g_G);
    cudaGetSymbolAddress(&p_thi, g_thi);   cudaGetSymbolAddress(&p_tlo, g_tlo);
    cudaGetSymbolAddress(&p_O, g_O);
    cudaGetSymbolAddress(&p_ohi, g_ohi);   cudaGetSymbolAddress(&p_olo, g_olo);
    cudaGetSymbolAddress(&p_GG, g_GG);     cudaGetSymbolAddress(&p_U, g_U);
    cudaGetSymbolAddress(&p_shi, g_shi);   cudaGetSymbolAddress(&p_slo, g_slo);

    const int T = 256;
    const int nBD = BATCH * DIM, nBH = BATCH * HID;

    // 1) all ternarizations in ONE launch
    TernArgs ta;
    ta.src[0] = wf;   ta.dst[0] = (__half*)p_wf;
    ta.src[1] = wc;   ta.dst[1] = (__half*)p_wc;
    ta.src[2] = wg;   ta.dst[2] = (__half*)p_wg;
    ta.src[3] = wo;   ta.dst[3] = (__half*)p_wo;
    ta.src[4] = wu;   ta.dst[4] = (__half*)p_wu;
    ta.src[5] = wg2;  ta.dst[5] = (__half*)p_wg2;
    ta.src[6] = wout; ta.dst[6] = (__half*)p_wout;
    long tern_chunks = 4L * (DIM*DIM/8) + 3L * (HID*DIM/8);
    tern_all_kernel<<<(unsigned)((tern_chunks + T - 1) / T), T>>>(ta);

    // 2) x -> hi/lo fp16
    split_kernel<<<(nBD/8 + T - 1)/T, T>>>((const float4*)x, (uint4*)p_xhi, (uint4*)p_xlo, nBD/8);

    dim3 gridD(DIM / BN, BATCH / BM);   // (16, 32)
    dim3 gridH(HID / BN, BATCH / BM);   // (64, 32)

    // 3) F, C, G
    gemm_hmma<<<gridD, 256, GEMM_SMEM>>>((__half*)p_xhi, (__half*)p_xlo,
                                         (__half*)p_wf, bf_, (float*)p_F, BATCH, DIM, DIM, 1.0f);
    gemm_hmma<<<gridD, 256, GEMM_SMEM>>>((__half*)p_xhi, (__half*)p_xlo,
                                         (__half*)p_wc, bc,  (float*)p_C, BATCH, DIM, DIM, 1.0f);
    gemm_hmma<<<gridD, 256, GEMM_SMEM>>>((__half*)p_xhi, (__half*)p_xlo,
                                         (__half*)p_wg, bg,  (float*)p_G, BATCH, DIM, DIM, 1.0f);

    // 4) gate fuse -> t hi/lo
    mlgru_ew_kernel<<<(nBD/4 + T - 1)/T, T>>>(nBD/4);

    // 5) O = t @ Wo^T + bo ; O -> hi/lo
    gemm_hmma<<<gridD, 256, GEMM_SMEM>>>((__half*)p_thi, (__half*)p_tlo,
                                         (__half*)p_wo, bo, (float*)p_O, BATCH, DIM, DIM, 1.0f);
    split_kernel<<<(nBD/8 + T - 1)/T, T>>>((const float4*)p_O, (uint4*)p_ohi, (uint4*)p_olo, nBD/8);

    // 6) GG, U  (N=8192, K=2048)
    gemm_hmma<<<gridH, 256, GEMM_SMEM>>>((__half*)p_ohi, (__half*)p_olo,
                                         (__half*)p_wg2, bg2, (float*)p_GG, BATCH, HID, DIM, 1.0f);
    gemm_hmma<<<gridH, 256, GEMM_SMEM>>>((__half*)p_ohi, (__half*)p_olo,
                                         (__half*)p_wu,  bu,  (float*)p_U,  BATCH, HID, DIM, 1.0f);

    // 7) s = sigmoid(GG)*silu(U) / SSCALE  (hi/lo, overflow-safe)
    glu_ew_kernel<<<(nBH/4 + T - 1)/T, T>>>(nBH/4);

    // 8) out = SSCALE * (s/SSCALE) @ Wout^T + bout   (K=8192)
    gemm_hmma<<<gridD, 256, GEMM_SMEM>>>((__half*)p_shi, (__half*)p_slo,
                                         (__half*)p_wout, bout, out, BATCH, DIM, HID, SSCALE);
}